// round 1
// baseline (speedup 1.0000x reference)
#include <cuda_runtime.h>
#include <math.h>

#define BATCH 4
#define T_SEQ 2048
#define TOK (BATCH*T_SEQ)          // 8192
#define DIMC 512
#define HEADS 8
#define DH 64
#define FRAMES 32

// ---------------- scratch (device globals: allocation-free rule) -------------
static __device__ float g_xn[TOK*DIMC];    // normalized x
static __device__ float g_q [TOK*DIMC];    // [B][H][T][64], pre-scaled by 1/8
static __device__ float g_k [TOK*DIMC];
static __device__ float g_v [TOK*DIMC];
static __device__ float g_att[TOK*DIMC];   // attention out, [B][T][H*64]

// ---------------- tf32 mma helpers ------------------------------------------
__device__ __forceinline__ unsigned f2tf(float x) {
    unsigned r; asm("cvt.rna.tf32.f32 %0, %1;" : "=r"(r) : "f"(x)); return r;
}
__device__ __forceinline__ void mma8(float* c, unsigned a0, unsigned a1,
                                     unsigned a2, unsigned a3,
                                     unsigned b0, unsigned b1) {
    asm volatile(
        "mma.sync.aligned.m16n8k8.row.col.f32.tf32.tf32.f32 "
        "{%0,%1,%2,%3},{%4,%5,%6,%7},{%8,%9},{%0,%1,%2,%3};\n"
        : "+f"(c[0]), "+f"(c[1]), "+f"(c[2]), "+f"(c[3])
        : "r"(a0), "r"(a1), "r"(a2), "r"(a3), "r"(b0), "r"(b1));
}

// ---------------- 1) LayerNorm: one warp per token ---------------------------
__global__ __launch_bounds__(256) void ln_kernel(
    const float* __restrict__ x, const float* __restrict__ gam,
    const float* __restrict__ bet)
{
    int warp = threadIdx.x >> 5, lane = threadIdx.x & 31;
    int tok  = blockIdx.x * 8 + warp;
    const float* xr = x + (size_t)tok * DIMC;
    float4 v[4]; float s = 0.f, ss = 0.f;
#pragma unroll
    for (int i = 0; i < 4; i++) {
        v[i] = *(const float4*)(xr + i * 128 + lane * 4);
        s  += v[i].x + v[i].y + v[i].z + v[i].w;
        ss += v[i].x*v[i].x + v[i].y*v[i].y + v[i].z*v[i].z + v[i].w*v[i].w;
    }
#pragma unroll
    for (int o = 16; o > 0; o >>= 1) {
        s  += __shfl_xor_sync(0xffffffffu, s, o);
        ss += __shfl_xor_sync(0xffffffffu, ss, o);
    }
    float mean = s * (1.f/512.f);
    float var  = ss * (1.f/512.f) - mean*mean;
    float rstd = rsqrtf(var + 1e-5f);
    float* orow = g_xn + (size_t)tok * DIMC;
#pragma unroll
    for (int i = 0; i < 4; i++) {
        int col = i * 128 + lane * 4;
        float4 g4 = *(const float4*)(gam + col);
        float4 b4 = *(const float4*)(bet + col);
        float4 r;
        r.x = (v[i].x - mean) * rstd * g4.x + b4.x;
        r.y = (v[i].y - mean) * rstd * g4.y + b4.y;
        r.z = (v[i].z - mean) * rstd * g4.z + b4.z;
        r.w = (v[i].w - mean) * rstd * g4.w + b4.w;
        *(float4*)(orow + col) = r;
    }
}

// ---------------- 2) QKV GEMM: 128x64x32 tiles, tf32 mma ---------------------
__global__ __launch_bounds__(256) void qkv_gemm(const float* __restrict__ Bw)
{
    __shared__ float As[128][36];
    __shared__ float Bs[32][72];
    const int N = 3 * DIMC, K = DIMC;
    int tid = threadIdx.x, warp = tid >> 5, lane = tid & 31;
    int g = lane >> 2, t4 = lane & 3;
    int wm = warp >> 1, wn = warp & 1;
    int row0 = blockIdx.y * 128, col0 = blockIdx.x * 64;
    const float* A = g_xn;
    float c[2][4][4] = {};

    for (int k0 = 0; k0 < K; k0 += 32) {
#pragma unroll
        for (int i = 0; i < 4; i++) {
            int idx = tid + i * 256;
            int r = idx >> 3, c4 = (idx & 7) * 4;
            float4 va = *(const float4*)(A + (size_t)(row0 + r) * K + k0 + c4);
            As[r][c4] = va.x; As[r][c4+1] = va.y; As[r][c4+2] = va.z; As[r][c4+3] = va.w;
        }
#pragma unroll
        for (int i = 0; i < 2; i++) {
            int idx = tid + i * 256;
            int r = idx >> 4, c4 = (idx & 15) * 4;
            float4 vb = *(const float4*)(Bw + (size_t)(k0 + r) * N + col0 + c4);
            Bs[r][c4] = vb.x; Bs[r][c4+1] = vb.y; Bs[r][c4+2] = vb.z; Bs[r][c4+3] = vb.w;
        }
        __syncthreads();
#pragma unroll
        for (int ks = 0; ks < 4; ks++) {
            int kb = ks * 8;
            unsigned a[2][4], b[4][2];
#pragma unroll
            for (int mi = 0; mi < 2; mi++) {
                int rb = wm * 32 + mi * 16;
                a[mi][0] = f2tf(As[rb + g    ][kb + t4    ]);
                a[mi][1] = f2tf(As[rb + g + 8][kb + t4    ]);
                a[mi][2] = f2tf(As[rb + g    ][kb + t4 + 4]);
                a[mi][3] = f2tf(As[rb + g + 8][kb + t4 + 4]);
            }
#pragma unroll
            for (int ni = 0; ni < 4; ni++) {
                int nb = wn * 32 + ni * 8;
                b[ni][0] = f2tf(Bs[kb + t4    ][nb + g]);
                b[ni][1] = f2tf(Bs[kb + t4 + 4][nb + g]);
            }
#pragma unroll
            for (int mi = 0; mi < 2; mi++)
#pragma unroll
                for (int ni = 0; ni < 4; ni++)
                    mma8(c[mi][ni], a[mi][0], a[mi][1], a[mi][2], a[mi][3],
                         b[ni][0], b[ni][1]);
        }
        __syncthreads();
    }
    int which = col0 >> 9;
    int h = (col0 & 511) >> 6;
    float* dst = (which == 0) ? g_q : ((which == 1) ? g_k : g_v);
    float sc = (which == 0) ? 0.125f : 1.0f;   // fold DIM_HEAD^-0.5 into q
#pragma unroll
    for (int mi = 0; mi < 2; mi++) {
        int r0 = row0 + wm * 32 + mi * 16 + g;
        int r1 = r0 + 8;
        int bb = r0 >> 11;
        int t0i = r0 & 2047, t1i = r1 & 2047;
        size_t base = (((size_t)bb * HEADS + h) * T_SEQ) * DH;
#pragma unroll
        for (int ni = 0; ni < 4; ni++) {
            int d = wn * 32 + ni * 8 + t4 * 2;
            size_t i0 = base + (size_t)t0i * DH + d;
            size_t i1 = base + (size_t)t1i * DH + d;
            dst[i0]     = c[mi][ni][0] * sc;
            dst[i0 + 1] = c[mi][ni][1] * sc;
            dst[i1]     = c[mi][ni][2] * sc;
            dst[i1 + 1] = c[mi][ni][3] * sc;
        }
    }
}

// ---------------- 3) frame-causal flash attention ----------------------------
#define QS_STR 68
#define KS_STR 68
#define VS_STR 72
#define PS_STR 68
#define ATTN_SMEM ((64*QS_STR + 64*KS_STR + 64*VS_STR + 4*16*PS_STR) * 4)

__global__ __launch_bounds__(128) void attn_kernel(float* __restrict__ gout)
{
    extern __shared__ float sm[];
    float* Qs = sm;
    float* Ks = Qs + 64 * QS_STR;
    float* Vs = Ks + 64 * KS_STR;
    float* Ps = Vs + 64 * VS_STR;

    int f = 31 - blockIdx.x;           // heavy frames first
    int h = blockIdx.y, b = blockIdx.z;
    int tid = threadIdx.x, warp = tid >> 5, lane = tid & 31;
    int g = lane >> 2, t4 = lane & 3;
    size_t bh = ((size_t)b * HEADS + h) * T_SEQ * DH;
    const float* qb = g_q + bh;
    const float* kb = g_k + bh;
    const float* vb = g_v + bh;
    int t0 = f * 64;

#pragma unroll
    for (int i = 0; i < 8; i++) {
        int idx = tid + i * 128;
        int r = idx >> 4, c4 = (idx & 15) * 4;
        float4 v = *(const float4*)(qb + (size_t)(t0 + r) * DH + c4);
        Qs[r*QS_STR + c4] = v.x; Qs[r*QS_STR + c4+1] = v.y;
        Qs[r*QS_STR + c4+2] = v.z; Qs[r*QS_STR + c4+3] = v.w;
    }

    float m0 = -1e30f, m1 = -1e30f, l0 = 0.f, l1 = 0.f;
    float o[8][4] = {};
    float* Pw = Ps + warp * 16 * PS_STR;
    int wrow = warp * 16;

    for (int kt = 0; kt <= f; kt++) {
        int kt0 = kt * 64;
#pragma unroll
        for (int i = 0; i < 8; i++) {
            int idx = tid + i * 128;
            int r = idx >> 4, c4 = (idx & 15) * 4;
            float4 vk = *(const float4*)(kb + (size_t)(kt0 + r) * DH + c4);
            float4 vv = *(const float4*)(vb + (size_t)(kt0 + r) * DH + c4);
            Ks[r*KS_STR + c4] = vk.x; Ks[r*KS_STR + c4+1] = vk.y;
            Ks[r*KS_STR + c4+2] = vk.z; Ks[r*KS_STR + c4+3] = vk.w;
            Vs[r*VS_STR + c4] = vv.x; Vs[r*VS_STR + c4+1] = vv.y;
            Vs[r*VS_STR + c4+2] = vv.z; Vs[r*VS_STR + c4+3] = vv.w;
        }
        __syncthreads();

        float s[8][4] = {};
#pragma unroll
        for (int ks = 0; ks < 8; ks++) {
            int kc = ks * 8;
            unsigned a0 = f2tf(Qs[(wrow + g    ) * QS_STR + kc + t4    ]);
            unsigned a1 = f2tf(Qs[(wrow + g + 8) * QS_STR + kc + t4    ]);
            unsigned a2 = f2tf(Qs[(wrow + g    ) * QS_STR + kc + t4 + 4]);
            unsigned a3 = f2tf(Qs[(wrow + g + 8) * QS_STR + kc + t4 + 4]);
#pragma unroll
            for (int n = 0; n < 8; n++) {
                unsigned b0 = f2tf(Ks[(n*8 + g) * KS_STR + kc + t4    ]);
                unsigned b1 = f2tf(Ks[(n*8 + g) * KS_STR + kc + t4 + 4]);
                mma8(s[n], a0, a1, a2, a3, b0, b1);
            }
        }

        float mx0 = -1e30f, mx1 = -1e30f;
#pragma unroll
        for (int n = 0; n < 8; n++) {
            mx0 = fmaxf(mx0, fmaxf(s[n][0], s[n][1]));
            mx1 = fmaxf(mx1, fmaxf(s[n][2], s[n][3]));
        }
        mx0 = fmaxf(mx0, __shfl_xor_sync(0xffffffffu, mx0, 1));
        mx0 = fmaxf(mx0, __shfl_xor_sync(0xffffffffu, mx0, 2));
        mx1 = fmaxf(mx1, __shfl_xor_sync(0xffffffffu, mx1, 1));
        mx1 = fmaxf(mx1, __shfl_xor_sync(0xffffffffu, mx1, 2));
        float mn0 = fmaxf(m0, mx0), mn1 = fmaxf(m1, mx1);
        float al0 = __expf(m0 - mn0), al1 = __expf(m1 - mn1);
        float sum0 = 0.f, sum1 = 0.f;
#pragma unroll
        for (int n = 0; n < 8; n++) {
            s[n][0] = __expf(s[n][0] - mn0);
            s[n][1] = __expf(s[n][1] - mn0);
            s[n][2] = __expf(s[n][2] - mn1);
            s[n][3] = __expf(s[n][3] - mn1);
            sum0 += s[n][0] + s[n][1];
            sum1 += s[n][2] + s[n][3];
        }
        sum0 += __shfl_xor_sync(0xffffffffu, sum0, 1);
        sum0 += __shfl_xor_sync(0xffffffffu, sum0, 2);
        sum1 += __shfl_xor_sync(0xffffffffu, sum1, 1);
        sum1 += __shfl_xor_sync(0xffffffffu, sum1, 2);
        l0 = l0 * al0 + sum0;  l1 = l1 * al1 + sum1;
        m0 = mn0;  m1 = mn1;
#pragma unroll
        for (int n = 0; n < 8; n++) {
            o[n][0] *= al0; o[n][1] *= al0;
            o[n][2] *= al1; o[n][3] *= al1;
        }

#pragma unroll
        for (int n = 0; n < 8; n++) {
            Pw[ g      * PS_STR + n*8 + t4*2    ] = s[n][0];
            Pw[ g      * PS_STR + n*8 + t4*2 + 1] = s[n][1];
            Pw[(g + 8) * PS_STR + n*8 + t4*2    ] = s[n][2];
            Pw[(g + 8) * PS_STR + n*8 + t4*2 + 1] = s[n][3];
        }
        __syncwarp();

#pragma unroll
        for (int ks = 0; ks < 8; ks++) {
            int kc = ks * 8;
            unsigned a0 = f2tf(Pw[ g      * PS_STR + kc + t4    ]);
            unsigned a1 = f2tf(Pw[(g + 8) * PS_STR + kc + t4    ]);
            unsigned a2 = f2tf(Pw[ g      * PS_STR + kc + t4 + 4]);
            unsigned a3 = f2tf(Pw[(g + 8) * PS_STR + kc + t4 + 4]);
#pragma unroll
            for (int n = 0; n < 8; n++) {
                unsigned b0 = f2tf(Vs[(kc + t4    ) * VS_STR + n*8 + g]);
                unsigned b1 = f2tf(Vs[(kc + t4 + 4) * VS_STR + n*8 + g]);
                mma8(o[n], a0, a1, a2, a3, b0, b1);
            }
        }
        __syncthreads();
    }

    float inv0 = 1.f / l0, inv1 = 1.f / l1;
    int q0 = t0 + wrow + g, q1 = q0 + 8;
    float* out0 = gout + ((size_t)b * T_SEQ + q0) * DIMC + h * DH;
    float* out1 = gout + ((size_t)b * T_SEQ + q1) * DIMC + h * DH;
#pragma unroll
    for (int n = 0; n < 8; n++) {
        int cc = n * 8 + t4 * 2;
        out0[cc]     = o[n][0] * inv0;
        out0[cc + 1] = o[n][1] * inv0;
        out1[cc]     = o[n][2] * inv1;
        out1[cc + 1] = o[n][3] * inv1;
    }
}

// ---------------- 4) output GEMM + bias --------------------------------------
__global__ __launch_bounds__(256) void out_gemm(
    const float* __restrict__ Bw, const float* __restrict__ bias,
    float* __restrict__ out)
{
    __shared__ float As[128][36];
    __shared__ float Bs[32][72];
    const int N = DIMC, K = DIMC;
    int tid = threadIdx.x, warp = tid >> 5, lane = tid & 31;
    int g = lane >> 2, t4 = lane & 3;
    int wm = warp >> 1, wn = warp & 1;
    int row0 = blockIdx.y * 128, col0 = blockIdx.x * 64;
    const float* A = g_att;
    float c[2][4][4] = {};

    for (int k0 = 0; k0 < K; k0 += 32) {
#pragma unroll
        for (int i = 0; i < 4; i++) {
            int idx = tid + i * 256;
            int r = idx >> 3, c4 = (idx & 7) * 4;
            float4 va = *(const float4*)(A + (size_t)(row0 + r) * K + k0 + c4);
            As[r][c4] = va.x; As[r][c4+1] = va.y; As[r][c4+2] = va.z; As[r][c4+3] = va.w;
        }
#pragma unroll
        for (int i = 0; i < 2; i++) {
            int idx = tid + i * 256;
            int r = idx >> 4, c4 = (idx & 15) * 4;
            float4 vb = *(const float4*)(Bw + (size_t)(k0 + r) * N + col0 + c4);
            Bs[r][c4] = vb.x; Bs[r][c4+1] = vb.y; Bs[r][c4+2] = vb.z; Bs[r][c4+3] = vb.w;
        }
        __syncthreads();
#pragma unroll
        for (int ks = 0; ks < 4; ks++) {
            int kb = ks * 8;
            unsigned a[2][4], b[4][2];
#pragma unroll
            for (int mi = 0; mi < 2; mi++) {
                int rb = wm * 32 + mi * 16;
                a[mi][0] = f2tf(As[rb + g    ][kb + t4    ]);
                a[mi][1] = f2tf(As[rb + g + 8][kb + t4    ]);
                a[mi][2] = f2tf(As[rb + g    ][kb + t4 + 4]);
                a[mi][3] = f2tf(As[rb + g + 8][kb + t4 + 4]);
            }
#pragma unroll
            for (int ni = 0; ni < 4; ni++) {
                int nb = wn * 32 + ni * 8;
                b[ni][0] = f2tf(Bs[kb + t4    ][nb + g]);
                b[ni][1] = f2tf(Bs[kb + t4 + 4][nb + g]);
            }
#pragma unroll
            for (int mi = 0; mi < 2; mi++)
#pragma unroll
                for (int ni = 0; ni < 4; ni++)
                    mma8(c[mi][ni], a[mi][0], a[mi][1], a[mi][2], a[mi][3],
                         b[ni][0], b[ni][1]);
        }
        __syncthreads();
    }
#pragma unroll
    for (int mi = 0; mi < 2; mi++) {
        int r0 = row0 + wm * 32 + mi * 16 + g;
        int r1 = r0 + 8;
#pragma unroll
        for (int ni = 0; ni < 4; ni++) {
            int col = col0 + wn * 32 + ni * 8 + t4 * 2;
            float bz0 = bias[col], bz1 = bias[col + 1];
            out[(size_t)r0 * N + col]     = c[mi][ni][0] + bz0;
            out[(size_t)r0 * N + col + 1] = c[mi][ni][1] + bz1;
            out[(size_t)r1 * N + col]     = c[mi][ni][2] + bz0;
            out[(size_t)r1 * N + col + 1] = c[mi][ni][3] + bz1;
        }
    }
}

// ---------------- launch -----------------------------------------------------
extern "C" void kernel_launch(void* const* d_in, const int* in_sizes, int n_in,
                              void* d_out, int out_size)
{
    (void)in_sizes; (void)n_in; (void)out_size;
    const float* x     = (const float*)d_in[0];
    const float* ln_g  = (const float*)d_in[1];
    const float* ln_b  = (const float*)d_in[2];
    const float* w_qkv = (const float*)d_in[3];
    const float* w_out = (const float*)d_in[4];
    const float* b_out = (const float*)d_in[5];
    float* out = (float*)d_out;

    cudaFuncSetAttribute(attn_kernel,
                         cudaFuncAttributeMaxDynamicSharedMemorySize, ATTN_SMEM);

    float* att_ptr = nullptr;
    cudaGetSymbolAddress((void**)&att_ptr, g_att);

    ln_kernel<<<TOK / 8, 256>>>(x, ln_g, ln_b);
    qkv_gemm<<<dim3(3 * DIMC / 64, TOK / 128), 256>>>(w_qkv);
    attn_kernel<<<dim3(FRAMES, HEADS, BATCH), 128, ATTN_SMEM>>>(att_ptr);
    out_gemm<<<dim3(DIMC / 64, TOK / 128), 256>>>(w_out, b_out, out);
}